// round 7
// baseline (speedup 1.0000x reference)
#include <cuda_runtime.h>

// RoI Align (AH=AW=14, spatial_scale=1/16).
// features: [2, 512, 100, 152] fp32, rois: [512, 5], out: [512, 512, 14, 14]
//
// Block = (roi, 64-channel chunk). Thread = bin (196 active of 256), bin
// coords/weights in registers. Patch staged channel-vectorized (float4 = 4
// channels per pixel) into double-buffered smem; staging gmem/patch offsets
// precomputed ONCE per block into registers and reused across all 16 groups.

#define AH 14
#define AW 14
#define NBINS (AH * AW)          // 196
#define C_TOT 512
#define FH 100
#define FW 152
#define PLANE (FH * FW)
#define SCALE 0.0625f
#define C_CHUNKS 8
#define C_PER (C_TOT / C_CHUNKS) // 64
#define NGRP (C_PER / 4)         // 16 groups of 4 channels
#define TH 256
#define MAXP 30
#define PITCH 30
#define MAXPIX (MAXP * PITCH)    // 900
#define MAXIT 4                  // ceil(900/256)

__global__ __launch_bounds__(TH)
void roi_align_kernel(const float* __restrict__ feat,
                      const float* __restrict__ rois,
                      float* __restrict__ out)
{
    __shared__ float4 s_patch[2][MAXPIX];        // 2 x 14.4 KB
    __shared__ int s_cx0, s_cy0, s_wcols, s_hrows;

    const int r   = blockIdx.x;
    const int tid = threadIdx.x;

    // roi params (broadcast loads)
    const float bf = __ldg(&rois[r * 5 + 0]);
    const float x1 = __ldg(&rois[r * 5 + 1]) * SCALE;
    const float y1 = __ldg(&rois[r * 5 + 2]) * SCALE;
    const float x2 = __ldg(&rois[r * 5 + 3]) * SCALE;
    const float y2 = __ldg(&rois[r * 5 + 4]) * SCALE;

    const float binw = fmaxf(x2 - x1, 0.0f) * (1.0f / 13.0f);
    const float binh = fmaxf(y2 - y1, 0.0f) * (1.0f / 13.0f);

    if (tid == 0) {
        const float sx0  = fminf(fmaxf(x1, 0.0f), (float)(FW - 1));
        const float sx13 = fminf(fmaxf(x1 + 13.0f * binw, 0.0f), (float)(FW - 1));
        const float sy0  = fminf(fmaxf(y1, 0.0f), (float)(FH - 1));
        const float sy13 = fminf(fmaxf(y1 + 13.0f * binh, 0.0f), (float)(FH - 1));
        const int cx0 = (int)floorf(sx0);
        const int cy0 = (int)floorf(sy0);
        s_cx0 = cx0;
        s_cy0 = cy0;
        s_wcols = (int)floorf(sx13) - cx0 + 2;   // <= 30
        s_hrows = (int)floorf(sy13) - cy0 + 2;   // <= 30
    }
    __syncthreads();

    const int cx0   = s_cx0;
    const int cy0   = s_cy0;
    const int wcols = s_wcols;
    const int npix  = s_hrows * wcols;

    const int c0 = blockIdx.y * C_PER;
    const float* __restrict__ fg =
        feat + (int)bf * (C_TOT * PLANE) + c0 * PLANE;
    float* __restrict__ ob = out + r * (C_TOT * NBINS) + c0 * NBINS + tid;

    // ---- per-thread bin coords (registers, fixed for whole kernel) ----
    int   o_idx = 0;
    float wx = 0.0f, wy = 0.0f;
    if (tid < NBINS) {
        const int ybin = tid / AW;
        const int xbin = tid - ybin * AW;
        const float xs = fminf(fmaxf(x1 + (float)xbin * binw, 0.0f), (float)(FW - 1));
        const float ys = fminf(fmaxf(y1 + (float)ybin * binh, 0.0f), (float)(FH - 1));
        const int x0 = (int)floorf(xs);
        const int y0 = (int)floorf(ys);
        wx = xs - (float)x0;
        wy = ys - (float)y0;
        o_idx = (y0 - cy0) * PITCH + (x0 - cx0);
    }

    // ---- staging offsets: computed ONCE, reused for all 16 groups ----
    int g_off[MAXIT];   // gmem pixel offset within a channel plane
    int p_idx[MAXIT];   // smem patch index, -1 if inactive
    #pragma unroll
    for (int j = 0; j < MAXIT; j++) {
        const int i = tid + j * TH;
        if (i < npix) {
            const int ry = i / wcols;
            const int rx = i - ry * wcols;
            g_off[j] = min(cy0 + ry, FH - 1) * FW + min(cx0 + rx, FW - 1);
            p_idx[j] = ry * PITCH + rx;
        } else {
            g_off[j] = 0;
            p_idx[j] = -1;
        }
    }

    // staging value registers
    float4 v[MAXIT];

    auto load_grp = [&]() {
        #pragma unroll
        for (int j = 0; j < MAXIT; j++) {
            if (p_idx[j] >= 0) {
                const float* __restrict__ p = fg + g_off[j];
                v[j].x = __ldg(p);
                v[j].y = __ldg(p + PLANE);
                v[j].z = __ldg(p + 2 * PLANE);
                v[j].w = __ldg(p + 3 * PLANE);
            }
        }
        fg += 4 * PLANE;   // advance to next 4-channel group
    };
    auto store_grp = [&](int buf) {
        #pragma unroll
        for (int j = 0; j < MAXIT; j++)
            if (p_idx[j] >= 0) s_patch[buf][p_idx[j]] = v[j];
    };

    // prologue: stage group 0
    load_grp();
    store_grp(0);
    __syncthreads();

    #pragma unroll 2
    for (int g = 0; g < NGRP; g++) {
        const int buf = g & 1;
        if (g + 1 < NGRP) load_grp();   // LDGs in flight over compute

        if (tid < NBINS) {
            const float4* __restrict__ p = s_patch[buf];
            const float4 t0 = p[o_idx];
            const float4 t1 = p[o_idx + 1];
            const float4 b0 = p[o_idx + PITCH];
            const float4 b1 = p[o_idx + PITCH + 1];

            float4 top, bot, vv;
            top.x = fmaf(wx, t1.x - t0.x, t0.x);
            top.y = fmaf(wx, t1.y - t0.y, t0.y);
            top.z = fmaf(wx, t1.z - t0.z, t0.z);
            top.w = fmaf(wx, t1.w - t0.w, t0.w);
            bot.x = fmaf(wx, b1.x - b0.x, b0.x);
            bot.y = fmaf(wx, b1.y - b0.y, b0.y);
            bot.z = fmaf(wx, b1.z - b0.z, b0.z);
            bot.w = fmaf(wx, b1.w - b0.w, b0.w);
            vv.x = fmaf(wy, bot.x - top.x, top.x);
            vv.y = fmaf(wy, bot.y - top.y, top.y);
            vv.z = fmaf(wy, bot.z - top.z, top.z);
            vv.w = fmaf(wy, bot.w - top.w, top.w);

            ob[0]         = vv.x;
            ob[NBINS]     = vv.y;
            ob[2 * NBINS] = vv.z;
            ob[3 * NBINS] = vv.w;
        }
        ob += 4 * NBINS;

        if (g + 1 < NGRP) store_grp(buf ^ 1);
        __syncthreads();
    }
}

extern "C" void kernel_launch(void* const* d_in, const int* in_sizes, int n_in,
                              void* d_out, int out_size)
{
    const float* feat = (const float*)d_in[0];
    const float* rois = (const float*)d_in[1];
    float* out = (float*)d_out;

    const int R = in_sizes[1] / 5;   // 512

    dim3 grid(R, C_CHUNKS, 1);
    dim3 block(TH, 1, 1);
    roi_align_kernel<<<grid, block>>>(feat, rois, out);
}